// round 3
// baseline (speedup 1.0000x reference)
#include <cuda_runtime.h>
#include <cuda_bf16.h>
#include <cstdint>
#include <math.h>

// ---------------- problem constants ----------------
#define TT_B   32           // batch
#define TT_N   2048         // neurons
#define NCTA   128          // persistent CTAs (single wave on 148 SMs)
#define NJ     16           // output columns per CTA (NCTA*NJ == TT_N)
#define TPB    512          // threads per CTA (16 warps)
#define CHUNK  256          // K rows staged per buffer
#define NCHUNK (TT_N / CHUNK)   // 8

// smem: Ws[2048][16] + buf[2][256][32] + red[512][16]
#define SMEM_FLOATS (TT_N*NJ + 2*CHUNK*TT_B + TPB*16)
#define SMEM_BYTES  (SMEM_FLOATS * 4)   // 229376

// persistent double-buffered s state: [parity][neuron][batch]
__device__ __align__(128) float g_s[2][TT_N][TT_B];
__device__ unsigned g_ctr;

__global__ void lif_init_kernel() { g_ctr = 0u; }

typedef unsigned long long ull;

// ---- packed fp32x2 helpers (FFMA2: 2x fp32 FMA throughput, PTX-only) ----
__device__ __forceinline__ void ffma2(ull &d, ull a, ull b) {
    asm("fma.rn.f32x2 %0, %1, %2, %0;" : "+l"(d) : "l"(a), "l"(b));
}
__device__ __forceinline__ ull pk2(float x, float y) {
    ull r; asm("mov.b64 %0, {%1,%2};" : "=l"(r) : "f"(x), "f"(y)); return r;
}
__device__ __forceinline__ void upk2(ull v, float &x, float &y) {
    asm("mov.b64 {%0,%1}, %2;" : "=f"(x), "=f"(y) : "l"(v));
}
__device__ __forceinline__ void cp16(uint32_t dst, const void* src) {
    asm volatile("cp.async.cg.shared.global [%0], [%1], 16;" :: "r"(dst), "l"(src));
}
__device__ __forceinline__ void cp_commit() { asm volatile("cp.async.commit_group;"); }
template<int N> __device__ __forceinline__ void cp_wait() {
    asm volatile("cp.async.wait_group %0;" :: "n"(N));
}

// Stage one chunk's per-warp row slice (16 rows x 32 floats, contiguous in
// both src and dst). Each warp stages ONLY the rows it will read -> no
// cross-warp sync needed, only __syncwarp.
__device__ __forceinline__ void stage_slice(const float* gsrc, float* buf,
                                            int chunk, int bsel, int ks, int lane) {
    const float* src = gsrc + (size_t)(chunk * CHUNK + ks * 16) * TT_B;
    float* dst = buf + bsel * (CHUNK * TT_B) + (ks * 16) * TT_B;
#pragma unroll
    for (int q = 0; q < 4; ++q) {
        int slot = lane + q * 32;                       // 128 float4 per slice
        uint32_t d = (uint32_t)__cvta_generic_to_shared(dst + slot * 4);
        cp16(d, src + slot * 4);
    }
}

__global__ void __launch_bounds__(TPB, 1)
lif_kernel(const float* __restrict__ x_in, const float* __restrict__ v0,
           const float* __restrict__ s0,   const float* __restrict__ w,
           const float* __restrict__ E_Lp, const float* __restrict__ tau_mp,
           const float* __restrict__ tau_sp, const int* __restrict__ ntype,
           float* __restrict__ out, int T)
{
    extern __shared__ float sm[];
    float* Ws  = sm;                        // [TT_N][NJ]
    float* buf = sm + TT_N * NJ;            // [2][CHUNK][TT_B]
    float* red = buf + 2 * CHUNK * TT_B;    // [TPB][16]

    const int tid  = threadIdx.x;
    const int lane = tid & 31;
    const int ks   = tid >> 5;              // warp id = K-split index
    const int pb   = lane & 15;             // batch-pair index
    const int cg   = lane >> 4;             // col-group (8 cols each)
    const int j0   = blockIdx.x * NJ;

    // ---- load + preprocess W slice: W_eff[i][j] = w[i][j]*nt[i], diag = 0 ----
    for (int idx = tid; idx < TT_N * NJ; idx += TPB) {
        int i = idx >> 4, jj = idx & 15;
        float val = w[(size_t)i * TT_N + (j0 + jj)] * (float)ntype[i];
        if (i == j0 + jj) val = 0.f;
        Ws[idx] = val;
    }

    // ---- epilogue-owned state: thread -> (batch eb, col ej) ----
    const int eb = tid >> 4;
    const int ej = tid & 15;
    const int jg = j0 + ej;
    float v = v0[eb * TT_N + jg];
    float s = s0[eb * TT_N + jg];
    g_s[0][jg][eb] = s;

    const float eL    = E_Lp[jg];
    const float tm    = tau_mp[jg];
    const float tsv   = tau_sp[jg];
    const float nR    = (30.0f - eL) * 1.1f;   // norm_R
    const float dvmax = 30.0f - eL;

    const int outI = eb * 16 + ej;
    const int rsw  = ((outI >> 5) ^ (outI & 15)) & 15;

    unsigned bar = 0;

    // ---- initial grid barrier: publish g_s[0] ----
    __threadfence();
    __syncthreads();
    bar += NCTA;
    if (tid == 0) {
        atomicAdd(&g_ctr, 1u);
        volatile unsigned* p = &g_ctr;
        while (*p < bar) { }
    }
    __syncthreads();

    for (int t = 0; t < T; ++t) {
        const int par = t & 1;
        const float* gsrc = &g_s[par][0][0];

        // prefetch this thread's input drive (DRAM latency hides under GEMM)
        const float xv = x_in[(size_t)t * (TT_B * TT_N) + eb * TT_N + jg];

        ull a00 = 0, a01 = 0, a02 = 0, a03 = 0;
        ull a10 = 0, a11 = 0, a12 = 0, a13 = 0;

        stage_slice(gsrc, buf, 0, 0, ks, lane); cp_commit();
        stage_slice(gsrc, buf, 1, 1, ks, lane); cp_commit();

        for (int c = 0; c < NCHUNK; ++c) {
            if (c < NCHUNK - 1) cp_wait<1>(); else cp_wait<0>();
            __syncwarp();
            const float* bc = buf + (c & 1) * (CHUNK * TT_B) + (ks * 16) * TT_B;
            const float* wr = Ws + (size_t)(c * CHUNK + ks * 16) * NJ + cg * 8;
#pragma unroll
            for (int r = 0; r < 16; ++r) {
                float2 sv = *(const float2*)(bc + r * TT_B + 2 * pb);
                float4 wa = *(const float4*)(wr + r * NJ);
                float4 wb = *(const float4*)(wr + r * NJ + 4);
                ull s0p = pk2(sv.x, sv.x);
                ull s1p = pk2(sv.y, sv.y);
                ull w01 = pk2(wa.x, wa.y), w23 = pk2(wa.z, wa.w);
                ull w45 = pk2(wb.x, wb.y), w67 = pk2(wb.z, wb.w);
                ffma2(a00, w01, s0p); ffma2(a01, w23, s0p);
                ffma2(a02, w45, s0p); ffma2(a03, w67, s0p);
                ffma2(a10, w01, s1p); ffma2(a11, w23, s1p);
                ffma2(a12, w45, s1p); ffma2(a13, w67, s1p);
            }
            if (c + 2 < NCHUNK) {
                __syncwarp();   // all lanes done reading buf[c&1] before restage
                stage_slice(gsrc, buf, c + 2, c & 1, ks, lane); cp_commit();
            }
        }

        // ---- K-split reduction via swizzled SMEM (<=2-way conflicts) ----
        {
            const int b0 = 2 * pb, b1 = 2 * pb + 1, cb = cg * 8;
            float lo, hi;
            auto st = [&](int b, int col, float val) {
                int o = b * 16 + col;
                int sw = ((o >> 5) ^ (o & 15)) & 15;
                red[o * 16 + (ks ^ sw)] = val;
            };
            upk2(a00, lo, hi); st(b0, cb + 0, lo); st(b0, cb + 1, hi);
            upk2(a01, lo, hi); st(b0, cb + 2, lo); st(b0, cb + 3, hi);
            upk2(a02, lo, hi); st(b0, cb + 4, lo); st(b0, cb + 5, hi);
            upk2(a03, lo, hi); st(b0, cb + 6, lo); st(b0, cb + 7, hi);
            upk2(a10, lo, hi); st(b1, cb + 0, lo); st(b1, cb + 1, hi);
            upk2(a11, lo, hi); st(b1, cb + 2, lo); st(b1, cb + 3, hi);
            upk2(a12, lo, hi); st(b1, cb + 4, lo); st(b1, cb + 5, hi);
            upk2(a13, lo, hi); st(b1, cb + 6, lo); st(b1, cb + 7, hi);
        }
        __syncthreads();

        float I = 0.f;
        {
            const float* rr = red + outI * 16;
#pragma unroll
            for (int k = 0; k < 16; ++k) I += rr[k ^ rsw];
        }
        I += 1.75f * xv;

        // ---- LIF dynamics (mirrors reference op order) ----
        float dv     = (eL - v + I * nR) / tm;
        float v_next = v + dv;
        float gating = fminf(fmaxf(v_next / 30.0f, 0.0f), 1.0f);
        float cdv    = fminf(fmaxf(dv / dvmax, 0.0f), 1.0f);
        s = s + (-s + gating * cdv) / tsv;
        out[(size_t)t * (TT_B * TT_N) + eb * TT_N + jg] =
            1.0f / (1.0f + expf(30.0f - v_next));
        v = (v_next >= 30.0f) ? eL : v_next;

        if (t + 1 < T) {
            g_s[par ^ 1][jg][eb] = s;
            // ---- grid barrier: all s published before anyone stages t+1 ----
            __threadfence();
            __syncthreads();
            bar += NCTA;
            if (tid == 0) {
                atomicAdd(&g_ctr, 1u);
                volatile unsigned* p = &g_ctr;
                while (*p < bar) { }
            }
            __syncthreads();
        }
    }
}

extern "C" void kernel_launch(void* const* d_in, const int* in_sizes, int n_in,
                              void* d_out, int out_size) {
    const float* x_in  = (const float*)d_in[0];
    const float* v0    = (const float*)d_in[1];
    const float* s0    = (const float*)d_in[2];
    const float* w     = (const float*)d_in[3];
    const float* E_L   = (const float*)d_in[4];
    const float* tau_m = (const float*)d_in[5];
    const float* tau_s = (const float*)d_in[6];
    const int*   ntype = (const int*)d_in[7];
    float* out = (float*)d_out;

    const int T = in_sizes[0] / (TT_B * TT_N);

    cudaFuncSetAttribute(lif_kernel,
                         cudaFuncAttributeMaxDynamicSharedMemorySize, SMEM_BYTES);

    lif_init_kernel<<<1, 1>>>();
    lif_kernel<<<NCTA, TPB, SMEM_BYTES>>>(x_in, v0, s0, w, E_L, tau_m, tau_s,
                                          ntype, out, T);
}

// round 5
// speedup vs baseline: 1.1744x; 1.1744x over previous
#include <cuda_runtime.h>
#include <cuda_bf16.h>
#include <cstdint>
#include <math.h>

// ---------------- configuration ----------------
#define TT_B   32
#define TT_N   2048
#define NCTA   128          // 16 colgroups x 8 K-splits (single wave)
#define TPB    512          // 16 warps = 8 mtiles x 2 khalves
#define CG_N   16
#define KS_N   8
#define KSLICE 256          // K per CTA
#define MTILE  128          // j per CTA

// SMEM layout
#define BPITCH   272                      // bytes per b-row (17*16, bank-clean)
#define BTILE    (TT_B * BPITCH)          // 8704 per (limb,khalf) tile
#define SM_B     0
#define SM_AL    (6 * BTILE)              // 52224 ; A_l per warp: 16j x 272B
#define ALW      (16 * BPITCH)            // 4352
#define SM_RED   (SM_AL + 16 * ALW)       // 121856 ; 8 mtiles x 16j x 160B
#define REDP     160
#define SM_TOTAL (SM_RED + 8 * 16 * REDP) // 142336

// ---------------- device globals ----------------
__device__ __align__(128) __nv_bfloat16 g_sT[2][3][TT_B][TT_N]; // [par][limb][b][k]
__device__ __align__(128) float g_part[NCTA][TT_B][MTILE];      // [cta][b][j]
__device__ unsigned g_ctr;

__global__ void lif_init_kernel() { g_ctr = 0u; }

// ---------------- helpers ----------------
__device__ __forceinline__ void mma_bf16(float* d, const uint32_t* a,
                                         uint32_t b0, uint32_t b1) {
    asm volatile("mma.sync.aligned.m16n8k16.row.col.f32.bf16.bf16.f32 "
                 "{%0,%1,%2,%3}, {%4,%5,%6,%7}, {%8,%9}, {%0,%1,%2,%3};"
                 : "+f"(d[0]), "+f"(d[1]), "+f"(d[2]), "+f"(d[3])
                 : "r"(a[0]), "r"(a[1]), "r"(a[2]), "r"(a[3]),
                   "r"(b0), "r"(b1));
}
__device__ __forceinline__ void cp16(uint32_t dst, const void* src) {
    asm volatile("cp.async.cg.shared.global [%0], [%1], 16;" :: "r"(dst), "l"(src));
}
__device__ __forceinline__ uint32_t smem_u32(const void* p) {
    uint32_t a;
    asm("{ .reg .u64 t; cvta.to.shared.u64 t, %1; cvt.u32.u64 %0, t; }" : "=r"(a) : "l"(p));
    return a;
}
// exact 3-way bf16 split (limbs sum to x within 2^-25 rel)
__device__ __forceinline__ void split3(float x, uint16_t& h, uint16_t& m, uint16_t& l) {
    __nv_bfloat16 bh = __float2bfloat16_rn(x);
    float r = x - __bfloat162float(bh);
    __nv_bfloat16 bm = __float2bfloat16_rn(r);
    float r2 = r - __bfloat162float(bm);
    __nv_bfloat16 bl = __float2bfloat16_rn(r2);
    h = __bfloat16_as_ushort(bh); m = __bfloat16_as_ushort(bm); l = __bfloat16_as_ushort(bl);
}

__global__ void __launch_bounds__(TPB, 1)
lif_kernel(const float* __restrict__ x_in, const float* __restrict__ v0,
           const float* __restrict__ s0,   const float* __restrict__ w,
           const float* __restrict__ E_Lp, const float* __restrict__ tau_mp,
           const float* __restrict__ tau_sp, const int* __restrict__ ntype,
           float* __restrict__ out, int T)
{
    extern __shared__ char smem[];
    const uint32_t smb = smem_u32(smem);

    const int tid   = threadIdx.x;
    const int lane  = tid & 31;
    const int wid   = tid >> 5;
    const int g     = lane >> 2;          // fragment group row
    const int tg    = lane & 3;           // thread-in-group
    const int cg    = blockIdx.x >> 3;    // colgroup 0..15
    const int ks    = blockIdx.x & 7;     // K-split 0..7
    const int khalf = wid & 1;
    const int mt    = wid >> 1;           // mtile 0..7

    const int jbase = cg * MTILE + mt * 16;               // warp's j range
    const int kbase = ks * KSLICE + khalf * 128;          // warp's k range

    // ---- one-time: build A fragments. Weff[k][j] = w[k][j]*nt[k], diag 0 ----
    auto weff = [&](int k, int j) -> float {
        if (k == j) return 0.f;
        return w[(size_t)k * TT_N + j] * (float)__ldg(&ntype[k]);
    };
    uint32_t a_h[8][4], a_m[8][4];
    {
        __nv_bfloat16* al = (__nv_bfloat16*)(smem + SM_AL + wid * ALW);
#pragma unroll
        for (int kst = 0; kst < 8; ++kst) {
            const int rows[2] = { g, g + 8 };
            const int kk0[2]  = { kst * 16 + 2 * tg, kst * 16 + 2 * tg + 8 };
#pragma unroll
            for (int q = 0; q < 4; ++q) {      // q = khalfsel*2 + rowsel
                int j = jbase + rows[q & 1];
                int k = kbase + kk0[q >> 1];
                uint16_t h0, m0, l0, h1, m1, l1;
                split3(weff(k,     j), h0, m0, l0);
                split3(weff(k + 1, j), h1, m1, l1);
                a_h[kst][q] = (uint32_t)h0 | ((uint32_t)h1 << 16);
                a_m[kst][q] = (uint32_t)m0 | ((uint32_t)m1 << 16);
            }
        }
        // fill A_l slice in SMEM: [jl 0..15][kl 0..127], pitch 272B
        for (int e = 0; e < 64; ++e) {
            int idx = lane + e * 32;
            int jl = idx >> 7, kl = idx & 127;
            uint16_t h, m, l;
            split3(weff(kbase + kl, jbase + jl), h, m, l);
            *(uint16_t*)((char*)al + jl * BPITCH + kl * 2) = l;
        }
    }

    // ---- dynamics ownership: tid = b*16 + m16 ----
    const int b   = tid >> 4;
    const int m16 = tid & 15;
    const int jg  = cg * MTILE + ks * 16 + m16;
    float v = v0[b * TT_N + jg];
    float s = s0[b * TT_N + jg];
    const float eL    = E_Lp[jg];
    const float tm    = tau_mp[jg];
    const float tsv   = tau_sp[jg];
    const float nR    = (30.0f - eL) * 1.1f;
    const float dvmax = 30.0f - eL;

    {   // publish initial s limbs (parity 0)
        uint16_t h, m, l; split3(s, h, m, l);
        g_sT[0][0][b][jg] = __ushort_as_bfloat16(h);
        g_sT[0][1][b][jg] = __ushort_as_bfloat16(m);
        g_sT[0][2][b][jg] = __ushort_as_bfloat16(l);
    }

    unsigned bar_tgt = 0;
    auto gbar = [&]() {
        __threadfence();
        __syncthreads();
        bar_tgt += NCTA;
        if (tid == 0) {
            atomicAdd(&g_ctr, 1u);
            volatile unsigned* p = &g_ctr;
            while (*p < bar_tgt) { }
        }
        __syncthreads();
    };

    __syncthreads();   // A_l visible intra-CTA
    gbar();            // initial s limbs visible chip-wide

    const char* albase = smem + SM_AL + wid * ALW;

    for (int t = 0; t < T; ++t) {
        const int par = t & 1;

        // ---- stage s limbs: 6 tiles x 512 16B-chunks, pitched SW layout ----
#pragma unroll
        for (int i = 0; i < 6; ++i) {
            int c    = tid + i * TPB;
            int tile = c >> 9;             // (limb*2 + khalf)
            int r    = c & 511;
            int bb   = r >> 4;
            int kc   = r & 15;
            const void* src = &g_sT[par][tile >> 1][bb]
                                  [ks * KSLICE + (tile & 1) * 128 + kc * 8];
            cp16(smb + SM_B + tile * BTILE + bb * BPITCH + kc * 16, src);
        }
        asm volatile("cp.async.commit_group;");

        // prefetch input drive
        const float xv = __ldg(&x_in[(size_t)t * (TT_B * TT_N) + b * TT_N + jg]);

        asm volatile("cp.async.wait_group 0;");
        __syncthreads();

        // ---- GEMM: 6 limb products, accumulate into D ----
        float d[4][4];
#pragma unroll
        for (int n = 0; n < 4; ++n)
#pragma unroll
            for (int q = 0; q < 4; ++q) d[n][q] = 0.f;

        const char* bh_base = smem + SM_B + (0 * 2 + khalf) * BTILE;
        const char* bm_base = smem + SM_B + (1 * 2 + khalf) * BTILE;
        const char* bl_base = smem + SM_B + (2 * 2 + khalf) * BTILE;

#pragma unroll
        for (int kst = 0; kst < 8; ++kst) {
            const int koff = kst * 32 + tg * 4;        // bytes within b-row
            // A_l fragments for this k-step (product Wl*Sh)
            uint32_t alr[4];
            alr[0] = *(const uint32_t*)(albase + g * BPITCH + koff);
            alr[1] = *(const uint32_t*)(albase + (g + 8) * BPITCH + koff);
            alr[2] = *(const uint32_t*)(albase + g * BPITCH + koff + 16);
            alr[3] = *(const uint32_t*)(albase + (g + 8) * BPITCH + koff + 16);
#pragma unroll
            for (int n = 0; n < 4; ++n) {
                const int row = (n * 8 + g) * BPITCH + koff;
                uint32_t bh0 = *(const uint32_t*)(bh_base + row);
                uint32_t bh1 = *(const uint32_t*)(bh_base + row + 16);
                uint32_t bm0 = *(const uint32_t*)(bm_base + row);
                uint32_t bm1 = *(const uint32_t*)(bm_base + row + 16);
                uint32_t bl0 = *(const uint32_t*)(bl_base + row);
                uint32_t bl1 = *(const uint32_t*)(bl_base + row + 16);
                mma_bf16(d[n], a_h[kst], bh0, bh1);   // Wh*Sh
                mma_bf16(d[n], a_h[kst], bm0, bm1);   // Wh*Sm
                mma_bf16(d[n], a_m[kst], bh0, bh1);   // Wm*Sh
                mma_bf16(d[n], a_m[kst], bm0, bm1);   // Wm*Sm
                mma_bf16(d[n], a_h[kst], bl0, bl1);   // Wh*Sl
                mma_bf16(d[n], alr,       bh0, bh1);  // Wl*Sh
            }
        }

        // ---- khalf pair-reduction via SMEM red[mt][j16][pitch160] ----
        {
            char* rbase = smem + SM_RED + mt * (16 * REDP);
            if (khalf == 1) {
#pragma unroll
                for (int n = 0; n < 4; ++n) {
                    char* p0 = rbase + g * REDP + (n * 8 + 2 * tg) * 4;
                    char* p1 = rbase + (g + 8) * REDP + (n * 8 + 2 * tg) * 4;
                    *(float2*)p0 = make_float2(d[n][0], d[n][1]);
                    *(float2*)p1 = make_float2(d[n][2], d[n][3]);
                }
            }
            __syncthreads();
            if (khalf == 0) {
#pragma unroll
                for (int n = 0; n < 4; ++n) {
                    const char* p0 = rbase + g * REDP + (n * 8 + 2 * tg) * 4;
                    const char* p1 = rbase + (g + 8) * REDP + (n * 8 + 2 * tg) * 4;
                    float2 r0 = *(const float2*)p0;
                    float2 r1 = *(const float2*)p1;
                    // store partial to global: g_part[cta][b][j]
                    float* gp = &g_part[blockIdx.x][0][0];
#pragma unroll
                    for (int q = 0; q < 4; ++q) {
                        float val = d[n][q] + ((q == 0) ? r0.x : (q == 1) ? r0.y
                                            : (q == 2) ? r1.x : r1.y);
                        int bb = n * 8 + 2 * tg + (q & 1);
                        int jj = mt * 16 + g + ((q >> 1) * 8);
                        gp[bb * MTILE + jj] = val;
                    }
                }
            }
        }

        gbar();   // partials visible chip-wide

        // ---- K-split reduce + LIF dynamics ----
        float I = 0.f;
        {
            const int jl = ks * 16 + m16;
#pragma unroll
            for (int kk = 0; kk < KS_N; ++kk)
                I += __ldcg(&g_part[cg * 8 + kk][b][jl]);
        }
        I += 1.75f * xv;

        float dv     = (eL - v + I * nR) / tm;
        float v_next = v + dv;
        float gating = fminf(fmaxf(v_next / 30.0f, 0.0f), 1.0f);
        float cdv    = fminf(fmaxf(dv / dvmax, 0.0f), 1.0f);
        s = s + (-s + gating * cdv) / tsv;
        out[(size_t)t * (TT_B * TT_N) + b * TT_N + jg] =
            1.0f / (1.0f + expf(30.0f - v_next));
        v = (v_next >= 30.0f) ? eL : v_next;

        if (t + 1 < T) {
            uint16_t h, m, l; split3(s, h, m, l);
            g_sT[par ^ 1][0][b][jg] = __ushort_as_bfloat16(h);
            g_sT[par ^ 1][1][b][jg] = __ushort_as_bfloat16(m);
            g_sT[par ^ 1][2][b][jg] = __ushort_as_bfloat16(l);
            gbar();   // s limbs visible before anyone stages t+1
        }
    }
}

extern "C" void kernel_launch(void* const* d_in, const int* in_sizes, int n_in,
                              void* d_out, int out_size) {
    const float* x_in  = (const float*)d_in[0];
    const float* v0    = (const float*)d_in[1];
    const float* s0    = (const float*)d_in[2];
    const float* w     = (const float*)d_in[3];
    const float* E_L   = (const float*)d_in[4];
    const float* tau_m = (const float*)d_in[5];
    const float* tau_s = (const float*)d_in[6];
    const int*   ntype = (const int*)d_in[7];
    float* out = (float*)d_out;

    const int T = in_sizes[0] / (TT_B * TT_N);

    cudaFuncSetAttribute(lif_kernel,
                         cudaFuncAttributeMaxDynamicSharedMemorySize, SM_TOTAL);

    lif_init_kernel<<<1, 1>>>();
    lif_kernel<<<NCTA, TPB, SM_TOTAL>>>(x_in, v0, s0, w, E_L, tau_m, tau_s,
                                        ntype, out, T);
}

// round 6
// speedup vs baseline: 1.2607x; 1.0734x over previous
#include <cuda_runtime.h>
#include <cuda_bf16.h>
#include <cstdint>
#include <math.h>

// ---------------- configuration ----------------
#define TT_B   32
#define TT_N   2048
#define NCTA   128          // 16 colgroups x 8 K-splits (single wave)
#define TPB    512          // 16 warps = 8 mtiles x 2 khalves
#define KS_N   8
#define KSLICE 256          // K per CTA
#define MTILE  128          // j per CTA

// SMEM layout
#define SM_B      0                        // 3 limb tiles [256 k][64B], swizzled
#define BTILE     16384
#define SM_AL     (3 * BTILE)              // 49152 ; A_l per warp: 16j x 272B
#define BPITCH    272
#define ALW       (16 * BPITCH)            // 4352
#define SM_RED    (SM_AL + 16 * ALW)       // 118784 ; 8 mtiles x 16j x 160B
#define REDP      160
#define SM_BOUNCE (SM_RED + 8 * 16 * REDP) // 139264 ; 48 rows x 64B
#define SM_MBAR   (SM_BOUNCE + 3072)       // 142336
#define SM_TOTAL  (SM_MBAR + 64)

// ---------------- device globals ----------------
// s limbs TRANSPOSED: [parity][limb][k(neuron)][b], 64B rows, chunk-swizzled
__device__ __align__(128) __nv_bfloat16 g_sT[2][3][TT_N][TT_B];
__device__ __align__(128) float g_part[NCTA][TT_B][MTILE];   // [cta][b][j]
__device__ unsigned g_ctr;

__global__ void lif_init_kernel() { g_ctr = 0u; }

// ---------------- helpers ----------------
__device__ __forceinline__ void mma_bf16(float* d, const uint32_t* a,
                                         uint32_t b0, uint32_t b1) {
    asm volatile("mma.sync.aligned.m16n8k16.row.col.f32.bf16.bf16.f32 "
                 "{%0,%1,%2,%3}, {%4,%5,%6,%7}, {%8,%9}, {%0,%1,%2,%3};"
                 : "+f"(d[0]), "+f"(d[1]), "+f"(d[2]), "+f"(d[3])
                 : "r"(a[0]), "r"(a[1]), "r"(a[2]), "r"(a[3]),
                   "r"(b0), "r"(b1));
}
__device__ __forceinline__ void ldmT(uint32_t* r, uint32_t addr) {
    asm volatile("ldmatrix.sync.aligned.m8n8.x4.trans.shared.b16 {%0,%1,%2,%3}, [%4];"
                 : "=r"(r[0]), "=r"(r[1]), "=r"(r[2]), "=r"(r[3]) : "r"(addr));
}
__device__ __forceinline__ uint32_t smem_u32(const void* p) {
    uint32_t a;
    asm("{ .reg .u64 t; cvta.to.shared.u64 t, %1; cvt.u32.u64 %0, t; }" : "=r"(a) : "l"(p));
    return a;
}
__device__ __forceinline__ void mbar_init(uint32_t mbar, uint32_t cnt) {
    asm volatile("mbarrier.init.shared.b64 [%0], %1;" :: "r"(mbar), "r"(cnt) : "memory");
}
__device__ __forceinline__ void mbar_arrive_tx(uint32_t mbar, uint32_t bytes) {
    asm volatile("mbarrier.arrive.expect_tx.shared.b64 _, [%0], %1;"
                 :: "r"(mbar), "r"(bytes) : "memory");
}
__device__ __forceinline__ void mbar_wait(uint32_t mbar, uint32_t parity) {
    asm volatile("{\n\t.reg .pred P1;\n\tWL%=:\n\t"
                 "mbarrier.try_wait.parity.acquire.cta.shared::cta.b64 P1, [%0], %1, 0x989680;\n\t"
                 "@P1 bra.uni WD%=;\n\tbra.uni WL%=;\n\tWD%=:\n\t}"
                 :: "r"(mbar), "r"(parity) : "memory");
}
__device__ __forceinline__ void bulk_cp(uint32_t dst, const void* src,
                                        uint32_t bytes, uint32_t mbar) {
    asm volatile("cp.async.bulk.shared::cluster.global.mbarrier::complete_tx::bytes "
                 "[%0], [%1], %2, [%3];"
                 :: "r"(dst), "l"(src), "r"(bytes), "r"(mbar) : "memory");
}
// exact 3-way bf16 split
__device__ __forceinline__ void split3(float x, uint16_t& h, uint16_t& m, uint16_t& l) {
    __nv_bfloat16 bh = __float2bfloat16_rn(x);
    float r = x - __bfloat162float(bh);
    __nv_bfloat16 bm = __float2bfloat16_rn(r);
    float r2 = r - __bfloat162float(bm);
    __nv_bfloat16 bl = __float2bfloat16_rn(r2);
    h = __bfloat16_as_ushort(bh); m = __bfloat16_as_ushort(bm); l = __bfloat16_as_ushort(bl);
}

__global__ void __launch_bounds__(TPB, 1)
lif_kernel(const float* __restrict__ x_in, const float* __restrict__ v0,
           const float* __restrict__ s0,   const float* __restrict__ w,
           const float* __restrict__ E_Lp, const float* __restrict__ tau_mp,
           const float* __restrict__ tau_sp, const int* __restrict__ ntype,
           float* __restrict__ out, int T)
{
    extern __shared__ char smem[];
    const uint32_t smb  = smem_u32(smem);
    const uint32_t mbar = smb + SM_MBAR;

    const int tid   = threadIdx.x;
    const int lane  = tid & 31;
    const int wid   = tid >> 5;
    const int g     = lane >> 2;
    const int tg    = lane & 3;
    const int cg    = blockIdx.x >> 3;
    const int ks    = blockIdx.x & 7;
    const int khalf = wid & 1;
    const int mt    = wid >> 1;

    const int jbase = cg * MTILE + mt * 16;
    const int kbase = ks * KSLICE + khalf * 128;

    if (tid == 0) mbar_init(mbar, 1);

    // ---- one-time A build: Weff[k][j] = w[k][j]*nt[k], diag 0 ----
    auto weff = [&](int k, int j) -> float {
        if (k == j) return 0.f;
        return w[(size_t)k * TT_N + j] * (float)__ldg(&ntype[k]);
    };
    uint32_t a_h[8][4], a_m[8][4];
    {
        __nv_bfloat16* al = (__nv_bfloat16*)(smem + SM_AL + wid * ALW);
#pragma unroll
        for (int kst = 0; kst < 8; ++kst) {
            const int rows[2] = { g, g + 8 };
            const int kk0[2]  = { kst * 16 + 2 * tg, kst * 16 + 2 * tg + 8 };
#pragma unroll
            for (int q = 0; q < 4; ++q) {
                int j = jbase + rows[q & 1];
                int k = kbase + kk0[q >> 1];
                uint16_t h0, m0, l0, h1, m1, l1;
                split3(weff(k,     j), h0, m0, l0);
                split3(weff(k + 1, j), h1, m1, l1);
                a_h[kst][q] = (uint32_t)h0 | ((uint32_t)h1 << 16);
                a_m[kst][q] = (uint32_t)m0 | ((uint32_t)m1 << 16);
            }
        }
        for (int e = 0; e < 64; ++e) {
            int idx = lane + e * 32;
            int jl = idx >> 7, kl = idx & 127;
            uint16_t h, m, l;
            split3(weff(kbase + kl, jbase + jl), h, m, l);
            *(uint16_t*)((char*)al + jl * BPITCH + kl * 2) = l;
        }
    }

    // ---- dynamics ownership: tid = b*16 + m16 ----
    const int b   = tid >> 4;
    const int m16 = tid & 15;
    const int j0  = cg * MTILE + ks * 16;
    const int jg  = j0 + m16;
    float v = v0[b * TT_N + jg];
    float s = s0[b * TT_N + jg];
    const float eL    = E_Lp[jg];
    const float tm    = tau_mp[jg];
    const float tsv   = tau_sp[jg];
    const float nR    = (30.0f - eL) * 1.1f;
    const float dvmax = 30.0f - eL;

    // swizzled byte offset of (b) within the 64B k-row of jg
    const int co = (((b >> 3) ^ ((jg >> 1) & 3)) * 16) + ((b & 7) * 2);

    {   // publish initial s limbs (parity 0), direct swizzled stores
        uint16_t h, m, l; split3(s, h, m, l);
        *(uint16_t*)((char*)&g_sT[0][0][jg][0] + co) = h;
        *(uint16_t*)((char*)&g_sT[0][1][jg][0] + co) = m;
        *(uint16_t*)((char*)&g_sT[0][2][jg][0] + co) = l;
    }

    unsigned bar_tgt = 0;
    auto gbar = [&]() {
        __threadfence();
        __syncthreads();
        bar_tgt += NCTA;
        if (tid == 0) {
            atomicAdd(&g_ctr, 1u);
            volatile unsigned* p = &g_ctr;
            while (*p < bar_tgt) { }
        }
        __syncthreads();
    };

    __syncthreads();   // A_l + mbar init visible intra-CTA
    gbar();            // initial s limbs visible chip-wide

    const char* albase = smem + SM_AL + wid * ALW;

    // ldmatrix lane address bases (swizzle independent of kst/limb)
    const int r8  = lane & 7;
    const int sel = lane >> 3;                 // m0..m3: bit0=k-half, bit1=n-half
    const int swl = (r8 >> 1) & 3;
    const int klrow = khalf * 128 + (sel & 1) * 8 + r8;
    const uint32_t ldm0 = smb + SM_B + klrow * 64 + (uint32_t)(((0 + (sel >> 1)) ^ swl) * 16);
    const uint32_t ldm1 = smb + SM_B + klrow * 64 + (uint32_t)(((2 + (sel >> 1)) ^ swl) * 16);

    for (int t = 0; t < T; ++t) {
        const int par = t & 1;

        // ---- stage s limbs: 3 contiguous 16KB bulk copies ----
        if (tid == 0) {
            mbar_arrive_tx(mbar, 3 * BTILE);
#pragma unroll
            for (int l = 0; l < 3; ++l)
                bulk_cp(smb + SM_B + l * BTILE, &g_sT[par][l][ks * KSLICE][0],
                        BTILE, mbar);
        }

        const float xv = __ldg(&x_in[(size_t)t * (TT_B * TT_N) + b * TT_N + jg]);

        mbar_wait(mbar, (uint32_t)(t & 1));

        // ---- GEMM: 6 limb products ----
        float d[4][4];
#pragma unroll
        for (int n = 0; n < 4; ++n)
#pragma unroll
            for (int q = 0; q < 4; ++q) d[n][q] = 0.f;

#pragma unroll
        for (int kst = 0; kst < 8; ++kst) {
            const uint32_t off = (uint32_t)kst * 1024;
            uint32_t bh[8], bm[8], bl[8];
            ldmT(bh + 0, ldm0 + 0 * BTILE + off);
            ldmT(bh + 4, ldm1 + 0 * BTILE + off);
            ldmT(bm + 0, ldm0 + 1 * BTILE + off);
            ldmT(bm + 4, ldm1 + 1 * BTILE + off);
            ldmT(bl + 0, ldm0 + 2 * BTILE + off);
            ldmT(bl + 4, ldm1 + 2 * BTILE + off);

            const int koff = kst * 32 + tg * 4;
            uint32_t alr[4];
            alr[0] = *(const uint32_t*)(albase + g * BPITCH + koff);
            alr[1] = *(const uint32_t*)(albase + (g + 8) * BPITCH + koff);
            alr[2] = *(const uint32_t*)(albase + g * BPITCH + koff + 16);
            alr[3] = *(const uint32_t*)(albase + (g + 8) * BPITCH + koff + 16);
#pragma unroll
            for (int n = 0; n < 4; ++n) {
                // frag reg mapping: n-tile n uses regs {2n mod 4} of op (n<2 ? lo : hi)
                const int i0 = (n & 1) * 2 + (n >> 1) * 4;
                mma_bf16(d[n], a_h[kst], bh[i0], bh[i0 + 1]);   // Wh*Sh
                mma_bf16(d[n], a_h[kst], bm[i0], bm[i0 + 1]);   // Wh*Sm
                mma_bf16(d[n], a_m[kst], bh[i0], bh[i0 + 1]);   // Wm*Sh
                mma_bf16(d[n], a_m[kst], bm[i0], bm[i0 + 1]);   // Wm*Sm
                mma_bf16(d[n], a_h[kst], bl[i0], bl[i0 + 1]);   // Wh*Sl
                mma_bf16(d[n], alr,       bh[i0], bh[i0 + 1]);  // Wl*Sh
            }
        }

        // wait: n-tile covers b rows n*8+g — but ldmatrix op1 covered b 0..15
        // (n-tiles 0,1) and op2 b 16..31 (n-tiles 2,3): mapping i0 must be
        // n0->{0,1} n1->{2,3} n2->{4,5} n3->{6,7}; i0 = n*2. (see below — fixed)

        // ---- khalf pair-reduction (unchanged from R5) ----
        {
            char* rbase = smem + SM_RED + mt * (16 * REDP);
            if (khalf == 1) {
#pragma unroll
                for (int n = 0; n < 4; ++n) {
                    char* p0 = rbase + g * REDP + (n * 8 + 2 * tg) * 4;
                    char* p1 = rbase + (g + 8) * REDP + (n * 8 + 2 * tg) * 4;
                    *(float2*)p0 = make_float2(d[n][0], d[n][1]);
                    *(float2*)p1 = make_float2(d[n][2], d[n][3]);
                }
            }
            __syncthreads();
            if (khalf == 0) {
#pragma unroll
                for (int n = 0; n < 4; ++n) {
                    const char* p0 = rbase + g * REDP + (n * 8 + 2 * tg) * 4;
                    const char* p1 = rbase + (g + 8) * REDP + (n * 8 + 2 * tg) * 4;
                    float2 r0 = *(const float2*)p0;
                    float2 r1 = *(const float2*)p1;
                    float* gp = &g_part[blockIdx.x][0][0];
#pragma unroll
                    for (int q = 0; q < 4; ++q) {
                        float val = d[n][q] + ((q == 0) ? r0.x : (q == 1) ? r0.y
                                            : (q == 2) ? r1.x : r1.y);
                        int bb = n * 8 + 2 * tg + (q & 1);
                        int jj = mt * 16 + g + ((q >> 1) * 8);
                        gp[bb * MTILE + jj] = val;
                    }
                }
            }
        }

        gbar();   // partials visible chip-wide

        // ---- K-split reduce + LIF dynamics ----
        float I = 0.f;
        {
            const int jl = ks * 16 + m16;
#pragma unroll
            for (int kk = 0; kk < KS_N; ++kk)
                I += __ldcg(&g_part[cg * 8 + kk][b][jl]);
        }
        I += 1.75f * xv;

        float dv     = (eL - v + I * nR) / tm;
        float v_next = v + dv;
        float gating = fminf(fmaxf(v_next / 30.0f, 0.0f), 1.0f);
        float cdv    = fminf(fmaxf(dv / dvmax, 0.0f), 1.0f);
        s = s + (-s + gating * cdv) / tsv;
        out[(size_t)t * (TT_B * TT_N) + b * TT_N + jg] =
            1.0f / (1.0f + expf(30.0f - v_next));
        v = (v_next >= 30.0f) ? eL : v_next;

        if (t + 1 < T) {
            // ---- publish s limbs via SMEM bounce + coalesced copy-out ----
            uint16_t h, m, l; split3(s, h, m, l);
            char* bb_ = smem + SM_BOUNCE;
            *(uint16_t*)(bb_ + (m16 * 3 + 0) * 64 + co) = h;
            *(uint16_t*)(bb_ + (m16 * 3 + 1) * 64 + co) = m;
            *(uint16_t*)(bb_ + (m16 * 3 + 2) * 64 + co) = l;
            __syncthreads();
            if (tid < 192) {
                const int ll = tid >> 6;           // limb
                const int rr = tid & 63;
                const int jl = rr >> 2;            // 0..15
                const int c  = rr & 3;
                const char* src = bb_ + (jl * 3 + ll) * 64 + c * 16;
                char* dst = (char*)&g_sT[par ^ 1][ll][j0 + jl][0] + c * 16;
                *(uint4*)dst = *(const uint4*)src;
            }
            gbar();   // s limbs visible before anyone stages t+1
        }
    }
}

extern "C" void kernel_launch(void* const* d_in, const int* in_sizes, int n_in,
                              void* d_out, int out_size) {
    const float* x_in  = (const float*)d_in[0];
    const float* v0    = (const float*)d_in[1];
    const float* s0    = (const float*)d_in[2];
    const float* w     = (const float*)d_in[3];
    const float* E_L   = (const float*)d_in[4];
    const float* tau_m = (const float*)d_in[5];
    const float* tau_s = (const float*)d_in[6];
    const int*   ntype = (const int*)d_in[7];
    float* out = (float*)d_out;

    const int T = in_sizes[0] / (TT_B * TT_N);

    cudaFuncSetAttribute(lif_kernel,
                         cudaFuncAttributeMaxDynamicSharedMemorySize, SM_TOTAL);

    lif_init_kernel<<<1, 1>>>();
    lif_kernel<<<NCTA, TPB, SM_TOTAL>>>(x_in, v0, s0, w, E_L, tau_m, tau_s,
                                        ntype, out, T);
}